// round 12
// baseline (speedup 1.0000x reference)
#include <cuda_runtime.h>
#include <cuda_bf16.h>

// Skipgram negative-sampling loss — ONE launch.
// Grid-wide reduction via a single packed u64 atomic (bit-deterministic).
//
// R11: multi-value butterfly reduction. The 11 per-lane partial dots are
// reduced JOINTLY (pad to 16, 4 halving exchange steps + xor16 = 16 SHFLs)
// instead of 11 independent 5-step butterflies (55 SHFLs). Afterwards each
// lane owns a distinct complete dot (index = bit-reversed lane&15), so
// log-sigmoid is evaluated once per warp across lanes (2 MUFU ops) instead
// of 11 redundant times (22). R10 A/B showed occupancy is not binding, so
// the extra 16 registers (launch_bounds 5 blocks/SM) are free.
//
// Inputs (metadata order):
//   d_in[0] input_idx  int32  [N]
//   d_in[1] output_idx int32  [N]
//   d_in[2] neg_idx    int32  [N, K]
//   d_in[3] W_in       fp32   [N_WORDS, D]
//   d_in[4] W_out      fp32   [N_WORDS, D]
// Output: scalar fp32 loss.

#define N_SAMPLES 65536
#define DIMS      128
#define KNEG      10
#define NROWS     (KNEG + 1)      // 11 W_out rows per sample
#define WARPS_PER_BLOCK 8
#define NBLOCKS   (N_SAMPLES / WARPS_PER_BLOCK)   // 8192
#define NTHREADS  (WARPS_PER_BLOCK * 32)          // 256

#define FP_BIAS   8192.0          // block partial is in (-8192, 0]
#define FP_SCALE  1048576.0       // 2^20

__device__ unsigned long long g_acc_pack;   // zero-initialized

__device__ __forceinline__ float warp_sum(float v) {
#pragma unroll
    for (int o = 16; o > 0; o >>= 1)
        v += __shfl_xor_sync(0xffffffff, v, o);
    return v;
}

// fast log(sigmoid(x)) = -log(1 + exp(-x)); safe for |x| << 80, rel err ~2^-21
__device__ __forceinline__ float logsig_fast(float x) {
    return -__logf(1.0f + __expf(-x));
}

__device__ __forceinline__ float dot4(float4 a, float4 b) {
    return a.x * b.x + a.y * b.y + a.z * b.z + a.w * b.w;
}

// cache policy: keep table lines resident in L2
__device__ __forceinline__ unsigned long long make_keep_policy() {
    unsigned long long pol;
    asm("createpolicy.fractional.L2::evict_last.b64 %0, 1.0;" : "=l"(pol));
    return pol;
}

// read-only float4 load with L2 keep-resident policy (LDG.128)
__device__ __forceinline__ float4 ldg_keep(const float4* p, unsigned long long pol) {
    float4 v;
    asm("ld.global.nc.L2::cache_hint.v4.f32 {%0,%1,%2,%3}, [%4], %5;"
        : "=f"(v.x), "=f"(v.y), "=f"(v.z), "=f"(v.w) : "l"(p), "l"(pol));
    return v;
}

__global__ __launch_bounds__(NTHREADS, 5)
void sg_compute_kernel(const int* __restrict__ input_idx,
                       const int* __restrict__ output_idx,
                       const int* __restrict__ neg_idx,
                       const float* __restrict__ W_in,
                       const float* __restrict__ W_out,
                       float* __restrict__ out) {
    const int tid  = threadIdx.x;
    const int warp = tid >> 5;
    const int lane = tid & 31;
    const int nbase = blockIdx.x * WARPS_PER_BLOCK;

    const unsigned long long pol = make_keep_policy();

    // --- stage the block's 96 indices through shared (coalesced loads) ---
    // layout: s_idx[w][0] = input idx, s_idx[w][1+j] = j-th W_out row (0=pos)
    __shared__ int s_idx[WARPS_PER_BLOCK][NROWS + 1];
    if (tid < WARPS_PER_BLOCK) {
        s_idx[tid][0] = input_idx[nbase + tid];
        s_idx[tid][1] = output_idx[nbase + tid];
    }
    if (tid < WARPS_PER_BLOCK * KNEG) {            // 80 consecutive ints
        int w = tid / KNEG, k = tid % KNEG;
        s_idx[w][2 + k] = neg_idx[nbase * KNEG + tid];
    }
    __syncthreads();

    // --- input row: each lane holds one float4 of the 128-float row ---
    float4 a = ldg_keep(reinterpret_cast<const float4*>(
                   W_in + (size_t)s_idx[warp][0] * DIMS) + lane, pol);

    // --- 3-deep rotated streaming of the 11 W_out rows: partial dots only ---
    float4 b0 = ldg_keep(reinterpret_cast<const float4*>(
                    W_out + (size_t)s_idx[warp][1] * DIMS) + lane, pol);
    float4 b1 = ldg_keep(reinterpret_cast<const float4*>(
                    W_out + (size_t)s_idx[warp][2] * DIMS) + lane, pol);
    float4 b2 = ldg_keep(reinterpret_cast<const float4*>(
                    W_out + (size_t)s_idx[warp][3] * DIMS) + lane, pol);

    float vals[16];
#pragma unroll
    for (int i = NROWS; i < 16; i++) vals[i] = 0.0f;

#pragma unroll
    for (int j = 0; j < NROWS; j++) {
        vals[j] = dot4(a, b0);
        b0 = b1;
        b1 = b2;
        if (j + 3 < NROWS)
            b2 = ldg_keep(reinterpret_cast<const float4*>(
                     W_out + (size_t)s_idx[warp][1 + j + 3] * DIMS) + lane, pol);
    }

    // --- joint multi-value butterfly: 16 values reduced in 15 SHFLs.
    // After step s, each lane tracks half as many values; which half is
    // selected by lane bit s. After 4 steps each lane holds ONE value,
    // index = bit-reverse of (lane & 15), summed over its 16-lane group.
#pragma unroll
    for (int s = 0; s < 4; s++) {
        const int nv = 8 >> s;               // 8,4,2,1
        const bool up = (lane >> s) & 1;
#pragma unroll
        for (int i = 0; i < nv; i++) {
            float send = up ? vals[i] : vals[i + nv];
            float keep = up ? vals[i + nv] : vals[i];
            vals[i] = keep + __shfl_xor_sync(0xffffffffu, send, 1 << s);
        }
    }
    // combine the two 16-lane groups -> full 32-lane dot on every lane
    float d = vals[0] + __shfl_xor_sync(0xffffffffu, vals[0], 16);

    // value id this lane owns: bit-reverse of lane&15
    const int v = ((lane & 1) << 3) | ((lane & 2) << 1) |
                  ((lane & 4) >> 1) | ((lane & 8) >> 3);

    // ONE log-sigmoid evaluation per warp (distinct dot per lane):
    // j==0 positive sample -> logsig(d); negatives -> logsig(-d)
    float x = (v == 0) ? d : -d;
    float contrib = (lane < 16 && v < NROWS) ? logsig_fast(x) : 0.0f;
    float local = warp_sum(contrib);          // this warp's sample loss

    // --- block reduce ---
    __shared__ float s_part[WARPS_PER_BLOCK];
    if (lane == 0) s_part[warp] = local;
    __syncthreads();
    if (tid == 0) {
        float t = 0.0f;
#pragma unroll
        for (int i = 0; i < WARPS_PER_BLOCK; i++) t += s_part[i];

        // fixed-point pack: value in [0, 2^34), counter at bit 48
        long long fixed = __double2ll_rn(((double)t + FP_BIAS) * FP_SCALE);
        unsigned long long add = (1ULL << 48) + (unsigned long long)fixed;
        unsigned long long old = atomicAdd(&g_acc_pack, add);

        if ((old >> 48) == NBLOCKS - 1) {
            // This block is last: old + add is the complete packed total.
            unsigned long long total = old + add;
            double sum = (double)(long long)(total & ((1ULL << 48) - 1)) / FP_SCALE
                         - (double)NBLOCKS * FP_BIAS;
            out[0] = (float)(sum / (double)N_SAMPLES);
            g_acc_pack = 0ULL;   // reset for next graph replay (no racers remain)
        }
    }
}

extern "C" void kernel_launch(void* const* d_in, const int* in_sizes, int n_in,
                              void* d_out, int out_size) {
    const int*   input_idx  = (const int*)d_in[0];
    const int*   output_idx = (const int*)d_in[1];
    const int*   neg_idx    = (const int*)d_in[2];
    const float* W_in       = (const float*)d_in[3];
    const float* W_out      = (const float*)d_in[4];
    float* out = (float*)d_out;

    sg_compute_kernel<<<NBLOCKS, NTHREADS>>>(
        input_idx, output_idx, neg_idx, W_in, W_out, out);
}